// round 14
// baseline (speedup 1.0000x reference)
#include <cuda_runtime.h>
#include <cuda_fp16.h>
#include <math.h>
#include <stdint.h>

constexpr int Bn = 4;
constexpr int Cd = 64;
constexpr int Hh = 256;
constexpr int Ww = 256;
constexpr int HWC = Hh * Ww;      // 65536
constexpr int Wh = 128;
constexpr int Nh = Hh * Wh;       // 32768

typedef unsigned long long ull;

// ---------------- scratch (alloc-free: __device__ globals) ----------------
__device__ __half g_t  [(size_t)Bn * Cd  * HWC];  //  33.5MB 1x1-conv temp (fp16)
__device__ float  g_qs [(size_t)Bn * Cd  * Nh ];  //  33.5MB squeezed q (raw)
__device__ float  g_ks [(size_t)Bn * Cd  * Nh ];  //  33.5MB squeezed k (raw, pre-softmax)
__device__ float  g_vs [(size_t)Bn * Cd  * Nh ];  //  33.5MB squeezed v
__device__ float  g_kmax[Bn * Cd];
__device__ float  g_kz [Bn * Cd];
__device__ float  g_ctxp[Bn * 4 * 8 * 256];       // 128 KB  partial ctx
__device__ float  g_att[(size_t)Bn * Cd  * Nh ];  //  33.5MB SQUEEZED att
__device__ float  g_attn[(size_t)Bn * 128 * HWC]; // 134 MB  attention (residual)
__device__ __half g_m1 [(size_t)Bn * 256 * HWC];  // 134 MB  (fp16)
__device__ __half g_m2 [(size_t)Bn * 256 * HWC];  // 134 MB  (fp16)

__device__ __forceinline__ float gelu_f(float x) {
    return 0.5f * x * (1.0f + erff(x * 0.7071067811865476f));
}

// -------- packed fp32x2 helpers --------
__device__ __forceinline__ ull bcast2(float x) {
    ull d; asm("mov.b64 %0, {%1, %1};" : "=l"(d) : "f"(x)); return d;
}
__device__ __forceinline__ ull pack2(float lo, float hi) {
    ull d; asm("mov.b64 %0, {%1, %2};" : "=l"(d) : "f"(lo), "f"(hi)); return d;
}
__device__ __forceinline__ void unpack2(float& lo, float& hi, ull d) {
    asm("mov.b64 {%0, %1}, %2;" : "=f"(lo), "=f"(hi) : "l"(d));
}
__device__ __forceinline__ void fma2(ull& d, ull a, ull b) {
    asm("fma.rn.f32x2 %0, %1, %2, %0;" : "+l"(d) : "l"(a), "l"(b));
}

// -------- typed 4-wide load/store --------
__device__ __forceinline__ float4 ld4(const float* p) { return *(const float4*)p; }
__device__ __forceinline__ float4 ld4(const __half* p) {
    __half2 a = *(const __half2*)p, b = *(const __half2*)(p + 2);
    float2 fa = __half22float2(a), fb = __half22float2(b);
    return make_float4(fa.x, fa.y, fb.x, fb.y);
}
__device__ __forceinline__ void st4(float* p, float4 v) { *(float4*)p = v; }
__device__ __forceinline__ void st4(__half* p, float4 v) {
    *(__half2*)p       = __floats2half2_rn(v.x, v.y);
    *(__half2*)(p + 2) = __floats2half2_rn(v.z, v.w);
}

// ---------------- 1x1 conv (scalar fp32x2, register-tiled, typed I/O) ----------------
// block 256 thr. tile: 128 px x OCT oc. thread: 4 px x (OCT/8) oc (paired).
// grid: (HW/128, OC/OCT, B). ACT: 0 none, 1 gelu, 2 +res(float)
template<typename Tin, typename Tout, int IC, int OC, int OCT, int ACT>
__global__ void __launch_bounds__(256)
conv1x1_v2_k(const Tin* __restrict__ in, const float* __restrict__ w,
             const float* __restrict__ bias, const float* __restrict__ res,
             Tout* __restrict__ out)
{
    constexpr int NO  = OCT / 8;
    constexpr int NP  = NO / 2;
    constexpr int SWP = OCT + 4;
    __shared__ __align__(16) float sX[16 * 128];
    __shared__ __align__(16) float sW[16 * SWP];

    const int b   = blockIdx.z;
    const int ocg = blockIdx.y;
    const int p0  = blockIdx.x * 128;
    const int pxb = (threadIdx.x & 31) * 4;
    const int ocb = (threadIdx.x >> 5) * NO;

    ull acc[NP * 4];
#pragma unroll
    for (int i = 0; i < NP * 4; i++) acc[i] = 0ULL;

    const Tin* inb = in + (size_t)b * IC * HWC + p0;
    const float* wb = w + (size_t)(ocg * OCT) * IC;

    for (int cc = 0; cc < IC; cc += 16) {
        __syncthreads();
        for (int t = threadIdx.x; t < 512; t += 256) {
            int ci = t >> 5, v = t & 31;
            float4 x = ld4(&inb[(size_t)(cc + ci) * HWC + v * 4]);
            *(float4*)&sX[ci * 128 + v * 4] = x;
        }
        for (int t = threadIdx.x; t < OCT * 4; t += 256) {
            int oc = t >> 2, u = t & 3;
            float4 wv = *(const float4*)&wb[(size_t)oc * IC + cc + u * 4];
            sW[(u * 4 + 0) * SWP + oc] = wv.x;
            sW[(u * 4 + 1) * SWP + oc] = wv.y;
            sW[(u * 4 + 2) * SWP + oc] = wv.z;
            sW[(u * 4 + 3) * SWP + oc] = wv.w;
        }
        __syncthreads();
#pragma unroll
        for (int ci = 0; ci < 16; ci++) {
            float4 xv = *(const float4*)&sX[ci * 128 + pxb];
            ull xx[4];
            xx[0] = bcast2(xv.x); xx[1] = bcast2(xv.y);
            xx[2] = bcast2(xv.z); xx[3] = bcast2(xv.w);
#pragma unroll
            for (int o4 = 0; o4 < NO / 4; o4++) {
                ulonglong2 wv = *(const ulonglong2*)&sW[ci * SWP + ocb + o4 * 4];
#pragma unroll
                for (int l = 0; l < 4; l++) {
                    fma2(acc[(o4 * 2 + 0) * 4 + l], wv.x, xx[l]);
                    fma2(acc[(o4 * 2 + 1) * 4 + l], wv.y, xx[l]);
                }
            }
        }
    }

    Tout* ob = out + ((size_t)b * OC + ocg * OCT + ocb) * HWC + p0 + pxb;
    const float* resb = (ACT == 2)
        ? (res + ((size_t)b * OC + ocg * OCT + ocb) * HWC + p0 + pxb) : nullptr;
#pragma unroll
    for (int op = 0; op < NP; op++) {
        float fl[4], fh[4];
#pragma unroll
        for (int l = 0; l < 4; l++) unpack2(fl[l], fh[l], acc[op * 4 + l]);
        const int o0 = 2 * op, o1 = 2 * op + 1;
        float b0 = __ldg(&bias[ocg * OCT + ocb + o0]);
        float b1 = __ldg(&bias[ocg * OCT + ocb + o1]);
        float4 v0 = make_float4(fl[0] + b0, fl[1] + b0, fl[2] + b0, fl[3] + b0);
        float4 v1 = make_float4(fh[0] + b1, fh[1] + b1, fh[2] + b1, fh[3] + b1);
        if (ACT == 1) {
            v0.x = gelu_f(v0.x); v0.y = gelu_f(v0.y); v0.z = gelu_f(v0.z); v0.w = gelu_f(v0.w);
            v1.x = gelu_f(v1.x); v1.y = gelu_f(v1.y); v1.z = gelu_f(v1.z); v1.w = gelu_f(v1.w);
        }
        if (ACT == 2) {
            float4 r0 = *(const float4*)&resb[(size_t)o0 * HWC];
            float4 r1 = *(const float4*)&resb[(size_t)o1 * HWC];
            v0.x += r0.x; v0.y += r0.y; v0.z += r0.z; v0.w += r0.w;
            v1.x += r1.x; v1.y += r1.y; v1.z += r1.z; v1.w += r1.w;
        }
        st4(&ob[(size_t)o0 * HWC], v0);
        st4(&ob[(size_t)o1 * HWC], v1);
    }
}

// ---------------- q/k 1x1 conv: ACTIVE PARITY ONLY (exact) ----------------
// Masked-input 1x1 conv output at inactive pixels == bias. Compute 128 active
// px of one row; write (val, bias) half2 pairs. sel: active j parity = (i+sel)&1.
// grid (Hh, 1, Bn), block 256. IC=OC=64. thread: 4 active px x 8 oc.
__global__ void __launch_bounds__(256)
conv1x1_qk_k(const float* __restrict__ in, const float* __restrict__ w,
             const float* __restrict__ bias, __half* __restrict__ out, int sel)
{
    constexpr int SWP = 68;
    __shared__ __align__(16) float sX[16 * 128];
    __shared__ __align__(16) float sW[16 * SWP];

    const int i  = blockIdx.x;
    const int b  = blockIdx.z;
    const int apar = (i + sel) & 1;
    const int pxb = (threadIdx.x & 31) * 4;   // active-px base
    const int ocb = (threadIdx.x >> 5) * 8;

    ull acc[16];
#pragma unroll
    for (int t = 0; t < 16; t++) acc[t] = 0ULL;

    const float* inb = in + (size_t)b * 64 * HWC + (size_t)i * Ww;

    for (int cc = 0; cc < 64; cc += 16) {
        __syncthreads();
        for (int t = threadIdx.x; t < 2048; t += 256) {
            int ci = t >> 7, ap = t & 127;
            sX[ci * 128 + ap] = inb[(size_t)(cc + ci) * HWC + 2 * ap + apar];
        }
        for (int t = threadIdx.x; t < 256; t += 256) {
            int oc = t >> 2, u = t & 3;
            float4 wv = *(const float4*)&w[(size_t)oc * 64 + cc + u * 4];
            sW[(u * 4 + 0) * SWP + oc] = wv.x;
            sW[(u * 4 + 1) * SWP + oc] = wv.y;
            sW[(u * 4 + 2) * SWP + oc] = wv.z;
            sW[(u * 4 + 3) * SWP + oc] = wv.w;
        }
        __syncthreads();
#pragma unroll
        for (int ci = 0; ci < 16; ci++) {
            float4 xv = *(const float4*)&sX[ci * 128 + pxb];
            ull xx[4];
            xx[0] = bcast2(xv.x); xx[1] = bcast2(xv.y);
            xx[2] = bcast2(xv.z); xx[3] = bcast2(xv.w);
#pragma unroll
            for (int o4 = 0; o4 < 2; o4++) {
                ulonglong2 wv = *(const ulonglong2*)&sW[ci * SWP + ocb + o4 * 4];
#pragma unroll
                for (int l = 0; l < 4; l++) {
                    fma2(acc[(o4 * 2 + 0) * 4 + l], wv.x, xx[l]);
                    fma2(acc[(o4 * 2 + 1) * 4 + l], wv.y, xx[l]);
                }
            }
        }
    }

    __half* ob = out + ((size_t)b * 64 + ocb) * HWC + (size_t)i * Ww;
#pragma unroll
    for (int op = 0; op < 4; op++) {
        float fl[4], fh[4];
#pragma unroll
        for (int l = 0; l < 4; l++) unpack2(fl[l], fh[l], acc[op * 4 + l]);
        const int o0 = 2 * op, o1 = 2 * op + 1;
        const float b0 = __ldg(&bias[ocb + o0]);
        const float b1 = __ldg(&bias[ocb + o1]);
        const __half hb0 = __float2half_rn(b0);
        const __half hb1 = __float2half_rn(b1);
#pragma unroll
        for (int l = 0; l < 4; l++) {
            const int jj = 2 * (pxb + l);
            __half hv0 = __float2half_rn(fl[l] + b0);
            __half hv1 = __float2half_rn(fh[l] + b1);
            *(__half2*)&ob[(size_t)o0 * HWC + jj] =
                apar ? __halves2half2(hb0, hv0) : __halves2half2(hv0, hb0);
            *(__half2*)&ob[(size_t)o1 * HWC + jj] =
                apar ? __halves2half2(hb1, hv1) : __halves2half2(hv1, hb1);
        }
    }
}

// ---------------- depthwise 3x3 + checkerboard squeeze (half input) ----------------
// block 128 thr = squeezed row; 4 output rows per block. grid (Hh/4, Bn*Cd).
__global__ void __launch_bounds__(128)
dw3x3_squeeze_k(const __half* __restrict__ in, const float* __restrict__ w,
                const float* __restrict__ bias, float* __restrict__ out, int type)
{
    __shared__ float sR[6][256];
    const int i0 = blockIdx.x * 4;
    const int bc = blockIdx.y;
    const int c  = bc & 63;
    const int jc = threadIdx.x;
    const __half* inp = in + (size_t)bc * HWC;

    for (int t = threadIdx.x; t < 384; t += 128) {
        int r = t >> 6, q = (t & 63) << 2;
        int ii = i0 - 1 + r;
        float4 v = make_float4(0.f, 0.f, 0.f, 0.f);
        if (ii >= 0 && ii < Hh) v = ld4(&inp[ii * Ww + q]);
        *(float4*)&sR[r][q] = v;
    }
    __syncthreads();

    float wk[9];
#pragma unroll
    for (int k = 0; k < 9; k++) wk[k] = __ldg(&w[c * 9 + k]);
    const float bv = __ldg(&bias[c]);

#pragma unroll
    for (int ry = 0; ry < 4; ry++) {
        const int i   = i0 + ry;
        const int sel = type ? (i & 1) : (1 - (i & 1));
        const int jf  = 2 * jc + sel;
        float acc = bv;
#pragma unroll
        for (int r = 0; r < 3; r++) {
            const float* row = sR[ry + r];
#pragma unroll
            for (int dx = -1; dx <= 1; dx++) {
                int jj = jf + dx;
                if (jj >= 0 && jj < Ww)
                    acc += wk[r * 3 + dx + 1] * row[jj];
            }
        }
        out[(size_t)bc * Nh + i * Wh + jc] = acc;
    }
}

// ---------------- depthwise 3x3 + gelu (half in/out, m2 path) ----------------
__global__ void __launch_bounds__(256)
dw3x3_gelu_k(const __half* __restrict__ in, const float* __restrict__ w,
             const float* __restrict__ bias, __half* __restrict__ out)
{
    __shared__ float sR[6][256];
    const int i0 = blockIdx.x * 4;
    const int bc = blockIdx.y;
    const int c  = bc & 255;
    const int j  = threadIdx.x;
    const __half* inp = in + (size_t)bc * HWC;

    for (int t = threadIdx.x; t < 384; t += 256) {
        int r = t >> 6, q = (t & 63) << 2;
        int ii = i0 - 1 + r;
        float4 v = make_float4(0.f, 0.f, 0.f, 0.f);
        if (ii >= 0 && ii < Hh) v = ld4(&inp[ii * Ww + q]);
        *(float4*)&sR[r][q] = v;
    }
    __syncthreads();

    float wk[9];
#pragma unroll
    for (int k = 0; k < 9; k++) wk[k] = __ldg(&w[c * 9 + k]);
    const float bv = __ldg(&bias[c]);

#pragma unroll
    for (int ry = 0; ry < 4; ry++) {
        float acc = bv;
#pragma unroll
        for (int r = 0; r < 3; r++) {
            const float* row = sR[ry + r];
#pragma unroll
            for (int dx = -1; dx <= 1; dx++) {
                int jj = j + dx;
                if (jj >= 0 && jj < Ww)
                    acc += wk[r * 3 + dx + 1] * row[jj];
            }
        }
        out[(size_t)bc * HWC + (i0 + ry) * Ww + j] = __float2half_rn(gelu_f(acc));
    }
}

// ---------------- k row stats: max and sum(exp(k-max)) per (b,c) row ----------------
__global__ void ksum_k(const float* __restrict__ ks)
{
    const size_t base = (size_t)blockIdx.x * Nh;
    __shared__ float red[256];
    float mx = -1e30f;
    for (int n = threadIdx.x; n < Nh; n += 256) mx = fmaxf(mx, ks[base + n]);
    red[threadIdx.x] = mx; __syncthreads();
    for (int s = 128; s > 0; s >>= 1) {
        if (threadIdx.x < s) red[threadIdx.x] = fmaxf(red[threadIdx.x], red[threadIdx.x + s]);
        __syncthreads();
    }
    mx = red[0]; __syncthreads();
    float sum = 0.f;
    for (int n = threadIdx.x; n < Nh; n += 256) sum += __expf(ks[base + n] - mx);
    red[threadIdx.x] = sum; __syncthreads();
    for (int s = 128; s > 0; s >>= 1) {
        if (threadIdx.x < s) red[threadIdx.x] += red[threadIdx.x + s];
        __syncthreads();
    }
    if (threadIdx.x == 0) { g_kmax[blockIdx.x] = mx; g_kz[blockIdx.x] = red[0]; }
}

// ---------------- ctx partials on exp(k-max): g_ctxp[bh][split][d*16+e] ----------------
__global__ void ctx_k(const float* __restrict__ ks, const float* __restrict__ vs)
{
    const int bh = blockIdx.x;
    const int b = bh >> 2, hd = bh & 3;
    const int d = threadIdx.x >> 4, e = threadIdx.x & 15;
    const float* kb = ks + ((size_t)b * Cd + hd * 16) * Nh;
    const float* vb = vs + ((size_t)b * Cd + hd * 16) * Nh;
    __shared__ __align__(16) float sk[16 * 260];
    __shared__ __align__(16) float sv[16 * 260];
    __shared__ float s_mx[16];
    if (threadIdx.x < 16)
        s_mx[threadIdx.x] = g_kmax[b * Cd + hd * 16 + threadIdx.x];
    float acc = 0.f;
    const int n00 = blockIdx.y * 4096;
    for (int n0 = n00; n0 < n00 + 4096; n0 += 256) {
        __syncthreads();
        for (int t = threadIdx.x; t < 4096; t += 256) {
            int dd = t >> 8, nn = t & 255;
            sk[dd * 260 + nn] = __expf(kb[(size_t)dd * Nh + n0 + nn] - s_mx[dd]);
            sv[dd * 260 + nn] = vb[(size_t)dd * Nh + n0 + nn];
        }
        __syncthreads();
#pragma unroll 4
        for (int nn = 0; nn < 256; nn++)
            acc += sk[d * 260 + nn] * sv[e * 260 + nn];
    }
    g_ctxp[((size_t)bh * 8 + blockIdx.y) * 256 + d * 16 + e] = acc;
}

// ---------------- att (SQUEEZED) with fused q-softmax + k normalization ----------------
__global__ void att_k(const float* __restrict__ qs, float* __restrict__ att_sq)
{
    const int bh = blockIdx.y;
    const int b = bh >> 2, hd = bh & 3;
    __shared__ float sc[256];
    {
        float s = 0.f;
#pragma unroll
        for (int sp = 0; sp < 8; sp++)
            s += g_ctxp[((size_t)bh * 8 + sp) * 256 + threadIdx.x];
        sc[threadIdx.x] = s / g_kz[b * Cd + hd * 16 + (threadIdx.x >> 4)];
    }
    __syncthreads();
    const int n = blockIdx.x * 256 + threadIdx.x;
    float qv[16];
    const float* qb = qs + ((size_t)b * Cd + hd * 16) * Nh + n;
    float mx = -1e30f;
#pragma unroll
    for (int d = 0; d < 16; d++) { qv[d] = qb[(size_t)d * Nh]; mx = fmaxf(mx, qv[d]); }
    float ssum = 0.f;
#pragma unroll
    for (int d = 0; d < 16; d++) { qv[d] = __expf(qv[d] - mx); ssum += qv[d]; }
    float inv = 1.0f / ssum;
#pragma unroll
    for (int d = 0; d < 16; d++) qv[d] *= inv;
    float* ab = att_sq + ((size_t)b * Cd + hd * 16) * Nh + n;
#pragma unroll
    for (int e = 0; e < 16; e++) {
        float s = 0.f;
#pragma unroll
        for (int d = 0; d < 16; d++) s += sc[d * 16 + e] * qv[d];
        ab[(size_t)e * Nh] = s;
    }
}

// ---------------- SPARSE 5x5 conv 64->128 on checkerboard input, fp32x2 ----------------
__global__ void __launch_bounds__(256)
conv5x5_sp_k(const float* __restrict__ in, const float* __restrict__ w,
             const float* __restrict__ bias, float* __restrict__ out)
{
    constexpr int CK = 4;
    __shared__ __align__(16) float sSq[CK * 240];
    __shared__ __align__(16) float sW[CK * 400];
    const int bz = blockIdx.z;
    const int b = bz >> 3, ocg = bz & 7;
    const int wid  = threadIdx.x >> 5;
    const int oq   = wid >> 1;
    const int qc   = wid & 1;
    const int lane = threadIdx.x & 31;
    const int py   = lane >> 1;
    const int m    = (lane & 1) * 4;
    const int x0 = blockIdx.x * 16, y0 = blockIdx.y * 16;
    const int p  = qc ^ (py & 1);

    ull acc[8];
    {
        float b0 = __ldg(&bias[ocg * 16 + oq * 4 + 0]);
        float b1 = __ldg(&bias[ocg * 16 + oq * 4 + 1]);
        float b2 = __ldg(&bias[ocg * 16 + oq * 4 + 2]);
        float b3 = __ldg(&bias[ocg * 16 + oq * 4 + 3]);
        ull p01 = pack2(b0, b1), p23 = pack2(b2, b3);
#pragma unroll
        for (int l = 0; l < 4; l++) { acc[l] = p01; acc[4 + l] = p23; }
    }

    const float* inb = in + (size_t)b * Cd * Nh;
    for (int cc = 0; cc < Cd; cc += CK) {
        __syncthreads();
#pragma unroll
        for (int c4 = 0; c4 < CK; c4++) {
            const int ci = cc + c4;
            for (int t = threadIdx.x; t < 200; t += 256) {
                int r = t / 10, s = t - r * 10;
                int ii = y0 - 2 + r;
                int jc = (x0 >> 1) - 1 + s;
                float v = 0.f;
                if (ii >= 0 && ii < Hh && jc >= 0 && jc < Wh)
                    v = inb[(size_t)ci * Nh + ii * Wh + jc];
                sSq[c4 * 240 + r * 12 + s] = v;
            }
            for (int t = threadIdx.x; t < 400; t += 256) {
                int ol = t & 15, k = t >> 4;
                sW[c4 * 400 + k * 16 + ol] = w[((size_t)(ocg * 16 + ol) * Cd + ci) * 25 + k];
            }
        }
        __syncthreads();
#pragma unroll
        for (int c4 = 0; c4 < CK; c4++) {
            const float* tile = &sSq[c4 * 240];
            const float* wt   = &sW[c4 * 400];
#pragma unroll
            for (int ky = 0; ky < 5; ky++) {
                const float* row = &tile[(py + ky) * 12 + m];
                if (((ky + qc) & 1) == 0) {
                    float4 a = *(const float4*)row;
                    ull xx[6];
                    xx[0] = bcast2(a.x); xx[1] = bcast2(a.y);
                    xx[2] = bcast2(a.z); xx[3] = bcast2(a.w);
                    xx[4] = bcast2(row[4]); xx[5] = bcast2(row[5]);
#pragma unroll
                    for (int kxh = 0; kxh < 3; kxh++) {
                        ulonglong2 wv = *(const ulonglong2*)&wt[(ky * 5 + 2 * kxh) * 16 + oq * 4];
#pragma unroll
                        for (int l = 0; l < 4; l++) {
                            fma2(acc[l],     wv.x, xx[l + kxh]);
                            fma2(acc[4 + l], wv.y, xx[l + kxh]);
                        }
                    }
                } else {
                    const float* rowp = row + p;
                    ull xx[5];
#pragma unroll
                    for (int j = 0; j < 5; j++) xx[j] = bcast2(rowp[j]);
#pragma unroll
                    for (int kxh = 0; kxh < 2; kxh++) {
                        ulonglong2 wv = *(const ulonglong2*)&wt[(ky * 5 + 2 * kxh + 1) * 16 + oq * 4];
#pragma unroll
                        for (int l = 0; l < 4; l++) {
                            fma2(acc[l],     wv.x, xx[l + kxh]);
                            fma2(acc[4 + l], wv.y, xx[l + kxh]);
                        }
                    }
                }
            }
        }
    }

    float* ob = out + ((size_t)b * 128 + ocg * 16 + oq * 4) * HWC
                    + (size_t)(y0 + py) * Ww + x0 + p + 2 * m;
#pragma unroll
    for (int l = 0; l < 4; l++) {
        float v0, v1, v2, v3;
        unpack2(v0, v1, acc[l]);
        unpack2(v2, v3, acc[4 + l]);
        ob[0 * (size_t)HWC + 2 * l] = v0;
        ob[1 * (size_t)HWC + 2 * l] = v1;
        ob[2 * (size_t)HWC + 2 * l] = v2;
        ob[3 * (size_t)HWC + 2 * l] = v3;
    }
}

// ---------------- driver ----------------
extern "C" void kernel_launch(void* const* d_in, const int* in_sizes, int n_in,
                              void* d_out, int out_size)
{
    const float* x1  = (const float*)d_in[0];
    const float* x2  = (const float*)d_in[1];
    const float* q1w = (const float*)d_in[2],  *q1b = (const float*)d_in[3];
    const float* q2w = (const float*)d_in[4],  *q2b = (const float*)d_in[5];
    const float* k1w = (const float*)d_in[6],  *k1b = (const float*)d_in[7];
    const float* k2w = (const float*)d_in[8],  *k2b = (const float*)d_in[9];
    const float* v1w = (const float*)d_in[10], *v1b = (const float*)d_in[11];
    const float* v2w = (const float*)d_in[12], *v2b = (const float*)d_in[13];
    const float* rw  = (const float*)d_in[14], *rb  = (const float*)d_in[15];
    const float* m1w = (const float*)d_in[16], *m1b = (const float*)d_in[17];
    const float* m2w = (const float*)d_in[18], *m2b = (const float*)d_in[19];
    const float* m3w = (const float*)d_in[20], *m3b = (const float*)d_in[21];
    float* out = (float*)d_out;

    __half *t, *m1, *m2;
    float *qs, *ks, *vs, *att, *attn;
    cudaGetSymbolAddress((void**)&t,    g_t);
    cudaGetSymbolAddress((void**)&qs,   g_qs);
    cudaGetSymbolAddress((void**)&ks,   g_ks);
    cudaGetSymbolAddress((void**)&vs,   g_vs);
    cudaGetSymbolAddress((void**)&att,  g_att);
    cudaGetSymbolAddress((void**)&attn, g_attn);
    cudaGetSymbolAddress((void**)&m1,   g_m1);
    cudaGetSymbolAddress((void**)&m2,   g_m2);

    // q/k: active-parity-only 1x1 conv -> depthwise 3x3 + squeeze
    conv1x1_qk_k<<<dim3(Hh, 1, Bn), 256>>>(x1, q1w, q1b, t, 0);               // keep (i+j) even
    dw3x3_squeeze_k<<<dim3(Hh / 4, Bn * Cd), 128>>>(t, q2w, q2b, qs, 1);      // nonanchor squeeze
    conv1x1_qk_k<<<dim3(Hh, 1, Bn), 256>>>(x1, k1w, k1b, t, 1);               // keep (i+j) odd
    dw3x3_squeeze_k<<<dim3(Hh / 4, Bn * Cd), 128>>>(t, k2w, k2b, ks, 0);      // anchor squeeze
    conv1x1_v2_k<float, __half, 64, 64, 64, 0>
        <<<dim3(HWC / 128, 1, Bn), 256>>>(x2, v1w, v1b, nullptr, t);          // v: no mask
    dw3x3_squeeze_k<<<dim3(Hh / 4, Bn * Cd), 128>>>(t, v2w, v2b, vs, 0);      // anchor squeeze

    // k-softmax fused: row stats, then ctx on exp(k-max), att divides by Z
    ksum_k<<<Bn * Cd, 256>>>(ks);
    ctx_k<<<dim3(Bn * 4, 8), 256>>>(ks, vs);
    att_k<<<dim3(Nh / 256, Bn * 4), 256>>>(qs, att);

    // attention = sparse conv5x5(att)
    conv5x5_sp_k<<<dim3(Ww / 16, Hh / 16, Bn * 8), 256>>>(att, rw, rb, attn);

    // MLP (fp32 math, fp16 intermediates): m1 (gelu) -> dw3x3 (gelu) -> m3 (+res)
    conv1x1_v2_k<float, __half, 128, 256, 128, 1>
        <<<dim3(HWC / 128, 2, Bn), 256>>>(attn, m1w, m1b, nullptr, m1);
    dw3x3_gelu_k<<<dim3(Hh / 4, Bn * 256), 256>>>(m1, m2w, m2b, m2);
    conv1x1_v2_k<__half, float, 256, 128, 128, 2>
        <<<dim3(HWC / 128, 1, Bn), 256>>>(m2, m3w, m3b, attn, out);
}

// round 15
// speedup vs baseline: 1.5815x; 1.5815x over previous
#include <cuda_runtime.h>
#include <math.h>
#include <stdint.h>

constexpr int Bn = 4;
constexpr int Cd = 64;
constexpr int Hh = 256;
constexpr int Ww = 256;
constexpr int HWC = Hh * Ww;      // 65536
constexpr int Wh = 128;
constexpr int Nh = Hh * Wh;       // 32768

typedef unsigned long long ull;

// ---------------- scratch (alloc-free: __device__ globals) ----------------
__device__ float g_t  [(size_t)Bn * Cd  * HWC];   //  67 MB  1x1-conv temp
__device__ float g_qs [(size_t)Bn * Cd  * Nh ];   //  33.5MB squeezed q (raw)
__device__ float g_ks [(size_t)Bn * Cd  * Nh ];   //  33.5MB squeezed k (raw, pre-softmax)
__device__ float g_vs [(size_t)Bn * Cd  * Nh ];   //  33.5MB squeezed v
__device__ float g_kmax[Bn * Cd];
__device__ float g_kz [Bn * Cd];
__device__ float g_ctxp[Bn * 4 * 8 * 256];        // 128 KB  partial ctx
__device__ float g_att[(size_t)Bn * Cd  * Nh ];   //  33.5MB SQUEEZED att
__device__ float g_attn[(size_t)Bn * 128 * HWC];  // 134 MB  attention (residual)
__device__ float g_m1 [(size_t)Bn * 256 * HWC];   // 268 MB
__device__ float g_m2 [(size_t)Bn * 256 * HWC];   // 268 MB

__device__ __forceinline__ float gelu_f(float x) {
    return 0.5f * x * (1.0f + erff(x * 0.7071067811865476f));
}

// -------- packed fp32x2 helpers --------
__device__ __forceinline__ ull bcast2(float x) {
    ull d; asm("mov.b64 %0, {%1, %1};" : "=l"(d) : "f"(x)); return d;
}
__device__ __forceinline__ ull pack2(float lo, float hi) {
    ull d; asm("mov.b64 %0, {%1, %2};" : "=l"(d) : "f"(lo), "f"(hi)); return d;
}
__device__ __forceinline__ void unpack2(float& lo, float& hi, ull d) {
    asm("mov.b64 {%0, %1}, %2;" : "=f"(lo), "=f"(hi) : "l"(d));
}
__device__ __forceinline__ void fma2(ull& d, ull a, ull b) {
    asm("fma.rn.f32x2 %0, %1, %2, %0;" : "+l"(d) : "l"(a), "l"(b));
}

// ---------------- 1x1 conv (scalar fp32x2, register-tiled) ----------------
// block 256 thr. tile: 128 px x OCT oc. thread: 4 px x (OCT/8) oc (paired).
// grid: (HW/128, OC/OCT, B). ACT: 0 none, 1 gelu, 2 +res
template<int IC, int OC, int OCT, int ACT>
__global__ void __launch_bounds__(256)
conv1x1_v2_k(const float* __restrict__ in, const float* __restrict__ w,
             const float* __restrict__ bias, const float* __restrict__ res,
             float* __restrict__ out)
{
    constexpr int NO  = OCT / 8;
    constexpr int NP  = NO / 2;
    constexpr int SWP = OCT + 4;
    __shared__ __align__(16) float sX[16 * 128];
    __shared__ __align__(16) float sW[16 * SWP];

    const int b   = blockIdx.z;
    const int ocg = blockIdx.y;
    const int p0  = blockIdx.x * 128;
    const int pxb = (threadIdx.x & 31) * 4;
    const int ocb = (threadIdx.x >> 5) * NO;

    ull acc[NP * 4];
#pragma unroll
    for (int i = 0; i < NP * 4; i++) acc[i] = 0ULL;

    const float* inb = in + (size_t)b * IC * HWC + p0;
    const float* wb  = w + (size_t)(ocg * OCT) * IC;

    for (int cc = 0; cc < IC; cc += 16) {
        __syncthreads();
        for (int t = threadIdx.x; t < 512; t += 256) {
            int ci = t >> 5, v = t & 31;
            float4 x = *(const float4*)&inb[(size_t)(cc + ci) * HWC + v * 4];
            *(float4*)&sX[ci * 128 + v * 4] = x;
        }
        for (int t = threadIdx.x; t < OCT * 4; t += 256) {
            int oc = t >> 2, u = t & 3;
            float4 wv = *(const float4*)&wb[(size_t)oc * IC + cc + u * 4];
            sW[(u * 4 + 0) * SWP + oc] = wv.x;
            sW[(u * 4 + 1) * SWP + oc] = wv.y;
            sW[(u * 4 + 2) * SWP + oc] = wv.z;
            sW[(u * 4 + 3) * SWP + oc] = wv.w;
        }
        __syncthreads();
#pragma unroll
        for (int ci = 0; ci < 16; ci++) {
            float4 xv = *(const float4*)&sX[ci * 128 + pxb];
            ull xx[4];
            xx[0] = bcast2(xv.x); xx[1] = bcast2(xv.y);
            xx[2] = bcast2(xv.z); xx[3] = bcast2(xv.w);
#pragma unroll
            for (int o4 = 0; o4 < NO / 4; o4++) {
                ulonglong2 wv = *(const ulonglong2*)&sW[ci * SWP + ocb + o4 * 4];
#pragma unroll
                for (int l = 0; l < 4; l++) {
                    fma2(acc[(o4 * 2 + 0) * 4 + l], wv.x, xx[l]);
                    fma2(acc[(o4 * 2 + 1) * 4 + l], wv.y, xx[l]);
                }
            }
        }
    }

    float* ob = out + ((size_t)b * OC + ocg * OCT + ocb) * HWC + p0 + pxb;
    const float* resb = (ACT == 2)
        ? (res + ((size_t)b * OC + ocg * OCT + ocb) * HWC + p0 + pxb) : nullptr;
#pragma unroll
    for (int op = 0; op < NP; op++) {
        float fl[4], fh[4];
#pragma unroll
        for (int l = 0; l < 4; l++) unpack2(fl[l], fh[l], acc[op * 4 + l]);
        const int o0 = 2 * op, o1 = 2 * op + 1;
        float b0 = __ldg(&bias[ocg * OCT + ocb + o0]);
        float b1 = __ldg(&bias[ocg * OCT + ocb + o1]);
        float4 v0 = make_float4(fl[0] + b0, fl[1] + b0, fl[2] + b0, fl[3] + b0);
        float4 v1 = make_float4(fh[0] + b1, fh[1] + b1, fh[2] + b1, fh[3] + b1);
        if (ACT == 1) {
            v0.x = gelu_f(v0.x); v0.y = gelu_f(v0.y); v0.z = gelu_f(v0.z); v0.w = gelu_f(v0.w);
            v1.x = gelu_f(v1.x); v1.y = gelu_f(v1.y); v1.z = gelu_f(v1.z); v1.w = gelu_f(v1.w);
        }
        if (ACT == 2) {
            float4 r0 = *(const float4*)&resb[(size_t)o0 * HWC];
            float4 r1 = *(const float4*)&resb[(size_t)o1 * HWC];
            v0.x += r0.x; v0.y += r0.y; v0.z += r0.z; v0.w += r0.w;
            v1.x += r1.x; v1.y += r1.y; v1.z += r1.z; v1.w += r1.w;
        }
        *(float4*)&ob[(size_t)o0 * HWC] = v0;
        *(float4*)&ob[(size_t)o1 * HWC] = v1;
    }
}

// ---------------- q/k 1x1 conv: ACTIVE PARITY ONLY (exact, fp32) ----------------
// Masked-input 1x1 conv output at inactive pixels == bias. Compute the 128
// active px of one row; write (val,bias) float2 pairs (full dense row).
// sel: active j parity = (i+sel)&1. grid (Hh, 1, Bn), block 256.
// thread: 4 active px x 8 oc. Staging: float4 over dense j, extract 2 active.
__global__ void __launch_bounds__(256)
conv1x1_qk_k(const float* __restrict__ in, const float* __restrict__ w,
             const float* __restrict__ bias, float* __restrict__ out, int sel)
{
    constexpr int SWP = 68;
    __shared__ __align__(16) float sX[16 * 128];
    __shared__ __align__(16) float sW[16 * SWP];

    const int i  = blockIdx.x;
    const int b  = blockIdx.z;
    const int apar = (i + sel) & 1;
    const int pxb = (threadIdx.x & 31) * 4;   // active-px base
    const int ocb = (threadIdx.x >> 5) * 8;

    ull acc[16];
#pragma unroll
    for (int t = 0; t < 16; t++) acc[t] = 0ULL;

    const float* inb = in + (size_t)b * 64 * HWC + (size_t)i * Ww;

    for (int cc = 0; cc < 64; cc += 16) {
        __syncthreads();
        // coalesced: float4 over 4 dense cols -> 2 active px each
        for (int t = threadIdx.x; t < 1024; t += 256) {
            int ci = t >> 6, g = t & 63;
            float4 v = *(const float4*)&inb[(size_t)(cc + ci) * HWC + 4 * g];
            sX[ci * 128 + 2 * g + 0] = apar ? v.y : v.x;
            sX[ci * 128 + 2 * g + 1] = apar ? v.w : v.z;
        }
        for (int t = threadIdx.x; t < 256; t += 256) {
            int oc = t >> 2, u = t & 3;
            float4 wv = *(const float4*)&w[(size_t)oc * 64 + cc + u * 4];
            sW[(u * 4 + 0) * SWP + oc] = wv.x;
            sW[(u * 4 + 1) * SWP + oc] = wv.y;
            sW[(u * 4 + 2) * SWP + oc] = wv.z;
            sW[(u * 4 + 3) * SWP + oc] = wv.w;
        }
        __syncthreads();
#pragma unroll
        for (int ci = 0; ci < 16; ci++) {
            float4 xv = *(const float4*)&sX[ci * 128 + pxb];
            ull xx[4];
            xx[0] = bcast2(xv.x); xx[1] = bcast2(xv.y);
            xx[2] = bcast2(xv.z); xx[3] = bcast2(xv.w);
#pragma unroll
            for (int o4 = 0; o4 < 2; o4++) {
                ulonglong2 wv = *(const ulonglong2*)&sW[ci * SWP + ocb + o4 * 4];
#pragma unroll
                for (int l = 0; l < 4; l++) {
                    fma2(acc[(o4 * 2 + 0) * 4 + l], wv.x, xx[l]);
                    fma2(acc[(o4 * 2 + 1) * 4 + l], wv.y, xx[l]);
                }
            }
        }
    }

    float* ob = out + ((size_t)b * 64 + ocb) * HWC + (size_t)i * Ww;
#pragma unroll
    for (int op = 0; op < 4; op++) {
        float fl[4], fh[4];
#pragma unroll
        for (int l = 0; l < 4; l++) unpack2(fl[l], fh[l], acc[op * 4 + l]);
        const int o0 = 2 * op, o1 = 2 * op + 1;
        const float b0 = __ldg(&bias[ocb + o0]);
        const float b1 = __ldg(&bias[ocb + o1]);
#pragma unroll
        for (int l = 0; l < 4; l++) {
            const int jj = 2 * (pxb + l);
            float v0 = fl[l] + b0, v1 = fh[l] + b1;
            *(float2*)&ob[(size_t)o0 * HWC + jj] =
                apar ? make_float2(b0, v0) : make_float2(v0, b0);
            *(float2*)&ob[(size_t)o1 * HWC + jj] =
                apar ? make_float2(b1, v1) : make_float2(v1, b1);
        }
    }
}

// ---------------- depthwise 3x3 + checkerboard squeeze (tiled) ----------------
// block 128 thr = squeezed row; 4 output rows per block via smem row cache.
// grid (Hh/4, Bn*Cd). type 0: anchor squeeze; 1: nonanchor.
__global__ void __launch_bounds__(128)
dw3x3_squeeze_k(const float* __restrict__ in, const float* __restrict__ w,
                const float* __restrict__ bias, float* __restrict__ out, int type)
{
    __shared__ float sR[6][256];
    const int i0 = blockIdx.x * 4;
    const int bc = blockIdx.y;
    const int c  = bc & 63;
    const int jc = threadIdx.x;
    const float* inp = in + (size_t)bc * HWC;

    for (int t = threadIdx.x; t < 384; t += 128) {
        int r = t >> 6, q = (t & 63) << 2;
        int ii = i0 - 1 + r;
        float4 v = make_float4(0.f, 0.f, 0.f, 0.f);
        if (ii >= 0 && ii < Hh) v = *(const float4*)&inp[ii * Ww + q];
        *(float4*)&sR[r][q] = v;
    }
    __syncthreads();

    float wk[9];
#pragma unroll
    for (int k = 0; k < 9; k++) wk[k] = __ldg(&w[c * 9 + k]);
    const float bv = __ldg(&bias[c]);

#pragma unroll
    for (int ry = 0; ry < 4; ry++) {
        const int i   = i0 + ry;
        const int sel = type ? (i & 1) : (1 - (i & 1));
        const int jf  = 2 * jc + sel;
        float acc = bv;
#pragma unroll
        for (int r = 0; r < 3; r++) {
            const float* row = sR[ry + r];
#pragma unroll
            for (int dx = -1; dx <= 1; dx++) {
                int jj = jf + dx;
                if (jj >= 0 && jj < Ww)
                    acc += wk[r * 3 + dx + 1] * row[jj];
            }
        }
        out[(size_t)bc * Nh + i * Wh + jc] = acc;
    }
}

// ---------------- depthwise 3x3 + gelu (tiled, m2 path) ----------------
__global__ void __launch_bounds__(256)
dw3x3_gelu_k(const float* __restrict__ in, const float* __restrict__ w,
             const float* __restrict__ bias, float* __restrict__ out)
{
    __shared__ float sR[6][256];
    const int i0 = blockIdx.x * 4;
    const int bc = blockIdx.y;
    const int c  = bc & 255;
    const int j  = threadIdx.x;
    const float* inp = in + (size_t)bc * HWC;

    for (int t = threadIdx.x; t < 384; t += 256) {
        int r = t >> 6, q = (t & 63) << 2;
        int ii = i0 - 1 + r;
        float4 v = make_float4(0.f, 0.f, 0.f, 0.f);
        if (ii >= 0 && ii < Hh) v = *(const float4*)&inp[ii * Ww + q];
        *(float4*)&sR[r][q] = v;
    }
    __syncthreads();

    float wk[9];
#pragma unroll
    for (int k = 0; k < 9; k++) wk[k] = __ldg(&w[c * 9 + k]);
    const float bv = __ldg(&bias[c]);

#pragma unroll
    for (int ry = 0; ry < 4; ry++) {
        float acc = bv;
#pragma unroll
        for (int r = 0; r < 3; r++) {
            const float* row = sR[ry + r];
#pragma unroll
            for (int dx = -1; dx <= 1; dx++) {
                int jj = j + dx;
                if (jj >= 0 && jj < Ww)
                    acc += wk[r * 3 + dx + 1] * row[jj];
            }
        }
        out[(size_t)bc * HWC + (i0 + ry) * Ww + j] = gelu_f(acc);
    }
}

// ---------------- k row stats: max and sum(exp(k-max)) per (b,c) row ----------------
__global__ void ksum_k(const float* __restrict__ ks)
{
    const size_t base = (size_t)blockIdx.x * Nh;
    __shared__ float red[256];
    float mx = -1e30f;
    for (int n = threadIdx.x; n < Nh; n += 256) mx = fmaxf(mx, ks[base + n]);
    red[threadIdx.x] = mx; __syncthreads();
    for (int s = 128; s > 0; s >>= 1) {
        if (threadIdx.x < s) red[threadIdx.x] = fmaxf(red[threadIdx.x], red[threadIdx.x + s]);
        __syncthreads();
    }
    mx = red[0]; __syncthreads();
    float sum = 0.f;
    for (int n = threadIdx.x; n < Nh; n += 256) sum += __expf(ks[base + n] - mx);
    red[threadIdx.x] = sum; __syncthreads();
    for (int s = 128; s > 0; s >>= 1) {
        if (threadIdx.x < s) red[threadIdx.x] += red[threadIdx.x + s];
        __syncthreads();
    }
    if (threadIdx.x == 0) { g_kmax[blockIdx.x] = mx; g_kz[blockIdx.x] = red[0]; }
}

// ---------------- ctx partials on exp(k-max): g_ctxp[bh][split][d*16+e] ----------------
__global__ void ctx_k(const float* __restrict__ ks, const float* __restrict__ vs)
{
    const int bh = blockIdx.x;
    const int b = bh >> 2, hd = bh & 3;
    const int d = threadIdx.x >> 4, e = threadIdx.x & 15;
    const float* kb = ks + ((size_t)b * Cd + hd * 16) * Nh;
    const float* vb = vs + ((size_t)b * Cd + hd * 16) * Nh;
    __shared__ __align__(16) float sk[16 * 260];
    __shared__ __align__(16) float sv[16 * 260];
    __shared__ float s_mx[16];
    if (threadIdx.x < 16)
        s_mx[threadIdx.x] = g_kmax[b * Cd + hd * 16 + threadIdx.x];
    float acc = 0.f;
    const int n00 = blockIdx.y * 4096;
    for (int n0 = n00; n0 < n00 + 4096; n0 += 256) {
        __syncthreads();
        for (int t = threadIdx.x; t < 4096; t += 256) {
            int dd = t >> 8, nn = t & 255;
            sk[dd * 260 + nn] = __expf(kb[(size_t)dd * Nh + n0 + nn] - s_mx[dd]);
            sv[dd * 260 + nn] = vb[(size_t)dd * Nh + n0 + nn];
        }
        __syncthreads();
#pragma unroll 4
        for (int nn = 0; nn < 256; nn++)
            acc += sk[d * 260 + nn] * sv[e * 260 + nn];
    }
    g_ctxp[((size_t)bh * 8 + blockIdx.y) * 256 + d * 16 + e] = acc;
}

// ---------------- att (SQUEEZED) with fused q-softmax + k normalization ----------------
__global__ void att_k(const float* __restrict__ qs, float* __restrict__ att_sq)
{
    const int bh = blockIdx.y;
    const int b = bh >> 2, hd = bh & 3;
    __shared__ float sc[256];
    {
        float s = 0.f;
#pragma unroll
        for (int sp = 0; sp < 8; sp++)
            s += g_ctxp[((size_t)bh * 8 + sp) * 256 + threadIdx.x];
        sc[threadIdx.x] = s / g_kz[b * Cd + hd * 16 + (threadIdx.x >> 4)];
    }
    __syncthreads();
    const int n = blockIdx.x * 256 + threadIdx.x;
    float qv[16];
    const float* qb = qs + ((size_t)b * Cd + hd * 16) * Nh + n;
    float mx = -1e30f;
#pragma unroll
    for (int d = 0; d < 16; d++) { qv[d] = qb[(size_t)d * Nh]; mx = fmaxf(mx, qv[d]); }
    float ssum = 0.f;
#pragma unroll
    for (int d = 0; d < 16; d++) { qv[d] = __expf(qv[d] - mx); ssum += qv[d]; }
    float inv = 1.0f / ssum;
#pragma unroll
    for (int d = 0; d < 16; d++) qv[d] *= inv;
    float* ab = att_sq + ((size_t)b * Cd + hd * 16) * Nh + n;
#pragma unroll
    for (int e = 0; e < 16; e++) {
        float s = 0.f;
#pragma unroll
        for (int d = 0; d < 16; d++) s += sc[d * 16 + e] * qv[d];
        ab[(size_t)e * Nh] = s;
    }
}

// ---------------- SPARSE 5x5 conv 64->128 on checkerboard input, fp32x2 ----------------
__global__ void __launch_bounds__(256)
conv5x5_sp_k(const float* __restrict__ in, const float* __restrict__ w,
             const float* __restrict__ bias, float* __restrict__ out)
{
    constexpr int CK = 4;
    __shared__ __align__(16) float sSq[CK * 240];
    __shared__ __align__(16) float sW[CK * 400];
    const int bz = blockIdx.z;
    const int b = bz >> 3, ocg = bz & 7;
    const int wid  = threadIdx.x >> 5;
    const int oq   = wid >> 1;
    const int qc   = wid & 1;
    const int lane = threadIdx.x & 31;
    const int py   = lane >> 1;
    const int m    = (lane & 1) * 4;
    const int x0 = blockIdx.x * 16, y0 = blockIdx.y * 16;
    const int p  = qc ^ (py & 1);

    ull acc[8];
    {
        float b0 = __ldg(&bias[ocg * 16 + oq * 4 + 0]);
        float b1 = __ldg(&bias[ocg * 16 + oq * 4 + 1]);
        float b2 = __ldg(&bias[ocg * 16 + oq * 4 + 2]);
        float b3 = __ldg(&bias[ocg * 16 + oq * 4 + 3]);
        ull p01 = pack2(b0, b1), p23 = pack2(b2, b3);
#pragma unroll
        for (int l = 0; l < 4; l++) { acc[l] = p01; acc[4 + l] = p23; }
    }

    const float* inb = in + (size_t)b * Cd * Nh;
    for (int cc = 0; cc < Cd; cc += CK) {
        __syncthreads();
#pragma unroll
        for (int c4 = 0; c4 < CK; c4++) {
            const int ci = cc + c4;
            for (int t = threadIdx.x; t < 200; t += 256) {
                int r = t / 10, s = t - r * 10;
                int ii = y0 - 2 + r;
                int jc = (x0 >> 1) - 1 + s;
                float v = 0.f;
                if (ii >= 0 && ii < Hh && jc >= 0 && jc < Wh)
                    v = inb[(size_t)ci * Nh + ii * Wh + jc];
                sSq[c4 * 240 + r * 12 + s] = v;
            }
            for (int t = threadIdx.x; t < 400; t += 256) {
                int ol = t & 15, k = t >> 4;
                sW[c4 * 400 + k * 16 + ol] = w[((size_t)(ocg * 16 + ol) * Cd + ci) * 25 + k];
            }
        }
        __syncthreads();
#pragma unroll
        for (int c4 = 0; c4 < CK; c4++) {
            const float* tile = &sSq[c4 * 240];
            const float* wt   = &sW[c4 * 400];
#pragma unroll
            for (int ky = 0; ky < 5; ky++) {
                const float* row = &tile[(py + ky) * 12 + m];
                if (((ky + qc) & 1) == 0) {
                    float4 a = *(const float4*)row;
                    ull xx[6];
                    xx[0] = bcast2(a.x); xx[1] = bcast2(a.y);
                    xx[2] = bcast2(a.z); xx[3] = bcast2(a.w);
                    xx[4] = bcast2(row[4]); xx[5] = bcast2(row[5]);
#pragma unroll
                    for (int kxh = 0; kxh < 3; kxh++) {
                        ulonglong2 wv = *(const ulonglong2*)&wt[(ky * 5 + 2 * kxh) * 16 + oq * 4];
#pragma unroll
                        for (int l = 0; l < 4; l++) {
                            fma2(acc[l],     wv.x, xx[l + kxh]);
                            fma2(acc[4 + l], wv.y, xx[l + kxh]);
                        }
                    }
                } else {
                    const float* rowp = row + p;
                    ull xx[5];
#pragma unroll
                    for (int j = 0; j < 5; j++) xx[j] = bcast2(rowp[j]);
#pragma unroll
                    for (int kxh = 0; kxh < 2; kxh++) {
                        ulonglong2 wv = *(const ulonglong2*)&wt[(ky * 5 + 2 * kxh + 1) * 16 + oq * 4];
#pragma unroll
                        for (int l = 0; l < 4; l++) {
                            fma2(acc[l],     wv.x, xx[l + kxh]);
                            fma2(acc[4 + l], wv.y, xx[l + kxh]);
                        }
                    }
                }
            }
        }
    }

    float* ob = out + ((size_t)b * 128 + ocg * 16 + oq * 4) * HWC
                    + (size_t)(y0 + py) * Ww + x0 + p + 2 * m;
#pragma unroll
    for (int l = 0; l < 4; l++) {
        float v0, v1, v2, v3;
        unpack2(v0, v1, acc[l]);
        unpack2(v2, v3, acc[4 + l]);
        ob[0 * (size_t)HWC + 2 * l] = v0;
        ob[1 * (size_t)HWC + 2 * l] = v1;
        ob[2 * (size_t)HWC + 2 * l] = v2;
        ob[3 * (size_t)HWC + 2 * l] = v3;
    }
}

// ---------------- driver ----------------
extern "C" void kernel_launch(void* const* d_in, const int* in_sizes, int n_in,
                              void* d_out, int out_size)
{
    const float* x1  = (const float*)d_in[0];
    const float* x2  = (const float*)d_in[1];
    const float* q1w = (const float*)d_in[2],  *q1b = (const float*)d_in[3];
    const float* q2w = (const float*)d_in[4],  *q2b = (const float*)d_in[5];
    const float* k1w = (const float*)d_in[6],  *k1b = (const float*)d_in[7];
    const float* k2w = (const float*)d_in[8],  *k2b = (const float*)d_in[9];
    const float* v1w = (const float*)d_in[10], *v1b = (const float*)d_in[11];
    const float* v2w = (const float*)d_in[12], *v2b = (const float*)d_in[13];
    const float* rw  = (const float*)d_in[14], *rb  = (const float*)d_in[15];
    const float* m1w = (const float*)d_in[16], *m1b = (const float*)d_in[17];
    const float* m2w = (const float*)d_in[18], *m2b = (const float*)d_in[19];
    const float* m3w = (const float*)d_in[20], *m3b = (const float*)d_in[21];
    float* out = (float*)d_out;

    float *t, *qs, *ks, *vs, *att, *attn, *m1, *m2;
    cudaGetSymbolAddress((void**)&t,    g_t);
    cudaGetSymbolAddress((void**)&qs,   g_qs);
    cudaGetSymbolAddress((void**)&ks,   g_ks);
    cudaGetSymbolAddress((void**)&vs,   g_vs);
    cudaGetSymbolAddress((void**)&att,  g_att);
    cudaGetSymbolAddress((void**)&attn, g_attn);
    cudaGetSymbolAddress((void**)&m1,   g_m1);
    cudaGetSymbolAddress((void**)&m2,   g_m2);

    // q/k: active-parity-only 1x1 conv (exact) -> depthwise 3x3 + squeeze
    conv1x1_qk_k<<<dim3(Hh, 1, Bn), 256>>>(x1, q1w, q1b, t, 0);               // keep (i+j) even
    dw3x3_squeeze_k<<<dim3(Hh / 4, Bn * Cd), 128>>>(t, q2w, q2b, qs, 1);      // nonanchor squeeze
    conv1x1_qk_k<<<dim3(Hh, 1, Bn), 256>>>(x1, k1w, k1b, t, 1);               // keep (i+j) odd
    dw3x3_squeeze_k<<<dim3(Hh / 4, Bn * Cd), 128>>>(t, k2w, k2b, ks, 0);      // anchor squeeze
    conv1x1_v2_k<64, 64, 64, 0><<<dim3(HWC / 128, 1, Bn), 256>>>(x2, v1w, v1b, nullptr, t);
    dw3x3_squeeze_k<<<dim3(Hh / 4, Bn * Cd), 128>>>(t, v2w, v2b, vs, 0);      // anchor squeeze

    // k-softmax fused: row stats, ctx on exp(k-max), att divides by Z
    ksum_k<<<Bn * Cd, 256>>>(ks);
    ctx_k<<<dim3(Bn * 4, 8), 256>>>(ks, vs);
    att_k<<<dim3(Nh / 256, Bn * 4), 256>>>(qs, att);

    // attention = sparse conv5x5(att)
    conv5x5_sp_k<<<dim3(Ww / 16, Hh / 16, Bn * 8), 256>>>(att, rw, rb, attn);

    // MLP (scalar fp32x2): m1 (gelu) -> dw3x3 (gelu) -> m3 (+ residual)
    conv1x1_v2_k<128, 256, 128, 1><<<dim3(HWC / 128, 2, Bn), 256>>>(attn, m1w, m1b, nullptr, m1);
    dw3x3_gelu_k<<<dim3(Hh / 4, Bn * 256), 256>>>(m1, m2w, m2b, m2);
    conv1x1_v2_k<256, 128, 128, 2><<<dim3(HWC / 128, 1, Bn), 256>>>(m2, m3w, m3b, attn, out);
}

// round 16
// speedup vs baseline: 1.6408x; 1.0375x over previous
#include <cuda_runtime.h>
#include <cuda_fp16.h>
#include <math.h>
#include <stdint.h>

constexpr int Bn = 4;
constexpr int Cd = 64;
constexpr int Hh = 256;
constexpr int Ww = 256;
constexpr int HWC = Hh * Ww;      // 65536
constexpr int Wh = 128;
constexpr int Nh = Hh * Wh;       // 32768

typedef unsigned long long ull;

// ---------------- scratch (alloc-free: __device__ globals) ----------------
__device__ __half g_t  [(size_t)Bn * Cd  * HWC];  //  33.5MB qkv 1x1 temp (fp16)
__device__ float  g_qs [(size_t)Bn * Cd  * Nh ];  //  33.5MB squeezed q (fp32)
__device__ float  g_ks [(size_t)Bn * Cd  * Nh ];  //  33.5MB squeezed k (fp32)
__device__ float  g_vs [(size_t)Bn * Cd  * Nh ];  //  33.5MB squeezed v (fp32)
__device__ float  g_kmax[Bn * Cd];
__device__ float  g_kz [Bn * Cd];
__device__ float  g_ctxp[Bn * 4 * 8 * 256];       // 128 KB  partial ctx
__device__ float  g_att[(size_t)Bn * Cd  * Nh ];  //  33.5MB SQUEEZED att (fp32)
__device__ float  g_attn[(size_t)Bn * 128 * HWC]; // 134 MB  attention (fp32, residual)
__device__ __half g_m1 [(size_t)Bn * 256 * HWC];  // 134 MB  (fp16)
__device__ __half g_m2 [(size_t)Bn * 256 * HWC];  // 134 MB  (fp16)

__device__ __forceinline__ float gelu_f(float x) {
    return 0.5f * x * (1.0f + erff(x * 0.7071067811865476f));
}

// -------- packed fp32x2 helpers --------
__device__ __forceinline__ ull bcast2(float x) {
    ull d; asm("mov.b64 %0, {%1, %1};" : "=l"(d) : "f"(x)); return d;
}
__device__ __forceinline__ ull pack2(float lo, float hi) {
    ull d; asm("mov.b64 %0, {%1, %2};" : "=l"(d) : "f"(lo), "f"(hi)); return d;
}
__device__ __forceinline__ void unpack2(float& lo, float& hi, ull d) {
    asm("mov.b64 {%0, %1}, %2;" : "=f"(lo), "=f"(hi) : "l"(d));
}
__device__ __forceinline__ void fma2(ull& d, ull a, ull b) {
    asm("fma.rn.f32x2 %0, %1, %2, %0;" : "+l"(d) : "l"(a), "l"(b));
}

// -------- wide fp16<->fp32 helpers (16B granularity, the R14 fix) --------
// load 8 halfs (one uint4) -> two float4
__device__ __forceinline__ void ld8h(const __half* p, float4& lo, float4& hi) {
    uint4 u = *(const uint4*)p;
    __half2* hp = (__half2*)&u;
    float2 f0 = __half22float2(hp[0]);
    float2 f1 = __half22float2(hp[1]);
    float2 f2 = __half22float2(hp[2]);
    float2 f3 = __half22float2(hp[3]);
    lo = make_float4(f0.x, f0.y, f1.x, f1.y);
    hi = make_float4(f2.x, f2.y, f3.x, f3.y);
}
// store float4 (4 contiguous values) to typed out
__device__ __forceinline__ void st4v(float* p, float4 v) { *(float4*)p = v; }
__device__ __forceinline__ void st4v(__half* p, float4 v) {
    __half2 a = __floats2half2_rn(v.x, v.y);
    __half2 b = __floats2half2_rn(v.z, v.w);
    uint2 u;
    u.x = *(uint32_t*)&a;
    u.y = *(uint32_t*)&b;
    *(uint2*)p = u;
}

// ---------------- staging helpers for conv1x1 (16 ci x 128 px tile) ----------------
__device__ __forceinline__ void stageX(const float* base, float* sX, int tid) {
    // base points at (cc)*HWC within the input channel-plane block
    for (int t = tid; t < 512; t += 256) {
        int ci = t >> 5, v = t & 31;
        float4 x = *(const float4*)&base[(size_t)ci * HWC + v * 4];
        *(float4*)&sX[ci * 128 + v * 4] = x;
    }
}
__device__ __forceinline__ void stageX(const __half* base, float* sX, int tid) {
    for (int t = tid; t < 256; t += 256) {
        int ci = t >> 4, g = t & 15;          // 8 px per uint4
        float4 lo, hi;
        ld8h(&base[(size_t)ci * HWC + g * 8], lo, hi);
        float* dst = &sX[ci * 128 + g * 8];
        *(float4*)dst       = lo;
        *(float4*)(dst + 4) = hi;
    }
}

// ---------------- 1x1 conv (scalar fp32x2, register-tiled, typed I/O) ----------------
// block 256 thr. tile: 128 px x OCT oc. thread: 4 px x (OCT/8) oc (paired).
// grid: (HW/128, OC/OCT, B). ACT: 0 none, 1 gelu, 2 +res(float)
template<typename Tin, typename Tout, int IC, int OC, int OCT, int ACT>
__global__ void __launch_bounds__(256)
conv1x1_v2_k(const Tin* __restrict__ in, const float* __restrict__ w,
             const float* __restrict__ bias, const float* __restrict__ res,
             Tout* __restrict__ out)
{
    constexpr int NO  = OCT / 8;
    constexpr int NP  = NO / 2;
    constexpr int SWP = OCT + 4;
    __shared__ __align__(16) float sX[16 * 128];
    __shared__ __align__(16) float sW[16 * SWP];

    const int b   = blockIdx.z;
    const int ocg = blockIdx.y;
    const int p0  = blockIdx.x * 128;
    const int pxb = (threadIdx.x & 31) * 4;
    const int ocb = (threadIdx.x >> 5) * NO;

    ull acc[NP * 4];
#pragma unroll
    for (int i = 0; i < NP * 4; i++) acc[i] = 0ULL;

    const Tin* inb = in + (size_t)b * IC * HWC + p0;
    const float* wb = w + (size_t)(ocg * OCT) * IC;

    for (int cc = 0; cc < IC; cc += 16) {
        __syncthreads();
        stageX(inb + (size_t)cc * HWC, sX, threadIdx.x);
        for (int t = threadIdx.x; t < OCT * 4; t += 256) {
            int oc = t >> 2, u = t & 3;
            float4 wv = *(const float4*)&wb[(size_t)oc * IC + cc + u * 4];
            sW[(u * 4 + 0) * SWP + oc] = wv.x;
            sW[(u * 4 + 1) * SWP + oc] = wv.y;
            sW[(u * 4 + 2) * SWP + oc] = wv.z;
            sW[(u * 4 + 3) * SWP + oc] = wv.w;
        }
        __syncthreads();
#pragma unroll
        for (int ci = 0; ci < 16; ci++) {
            float4 xv = *(const float4*)&sX[ci * 128 + pxb];
            ull xx[4];
            xx[0] = bcast2(xv.x); xx[1] = bcast2(xv.y);
            xx[2] = bcast2(xv.z); xx[3] = bcast2(xv.w);
#pragma unroll
            for (int o4 = 0; o4 < NO / 4; o4++) {
                ulonglong2 wv = *(const ulonglong2*)&sW[ci * SWP + ocb + o4 * 4];
#pragma unroll
                for (int l = 0; l < 4; l++) {
                    fma2(acc[(o4 * 2 + 0) * 4 + l], wv.x, xx[l]);
                    fma2(acc[(o4 * 2 + 1) * 4 + l], wv.y, xx[l]);
                }
            }
        }
    }

    Tout* ob = out + ((size_t)b * OC + ocg * OCT + ocb) * HWC + p0 + pxb;
    const float* resb = (ACT == 2)
        ? (res + ((size_t)b * OC + ocg * OCT + ocb) * HWC + p0 + pxb) : nullptr;
#pragma unroll
    for (int op = 0; op < NP; op++) {
        float fl[4], fh[4];
#pragma unroll
        for (int l = 0; l < 4; l++) unpack2(fl[l], fh[l], acc[op * 4 + l]);
        const int o0 = 2 * op, o1 = 2 * op + 1;
        float b0 = __ldg(&bias[ocg * OCT + ocb + o0]);
        float b1 = __ldg(&bias[ocg * OCT + ocb + o1]);
        float4 v0 = make_float4(fl[0] + b0, fl[1] + b0, fl[2] + b0, fl[3] + b0);
        float4 v1 = make_float4(fh[0] + b1, fh[1] + b1, fh[2] + b1, fh[3] + b1);
        if (ACT == 1) {
            v0.x = gelu_f(v0.x); v0.y = gelu_f(v0.y); v0.z = gelu_f(v0.z); v0.w = gelu_f(v0.w);
            v1.x = gelu_f(v1.x); v1.y = gelu_f(v1.y); v1.z = gelu_f(v1.z); v1.w = gelu_f(v1.w);
        }
        if (ACT == 2) {
            float4 r0 = *(const float4*)&resb[(size_t)o0 * HWC];
            float4 r1 = *(const float4*)&resb[(size_t)o1 * HWC];
            v0.x += r0.x; v0.y += r0.y; v0.z += r0.z; v0.w += r0.w;
            v1.x += r1.x; v1.y += r1.y; v1.z += r1.z; v1.w += r1.w;
        }
        st4v(&ob[(size_t)o0 * HWC], v0);
        st4v(&ob[(size_t)o1 * HWC], v1);
    }
}

// ---------------- q/k 1x1 conv: ACTIVE PARITY ONLY (exact math, fp16 out) ----------------
// Output at inactive pixels == bias (exact). Writes full dense rows as packed
// 16B stores (4 half2 per oc-row per thread). sel: active j parity = (i+sel)&1.
// grid (Hh, 1, Bn), block 256. thread: 4 active px x 8 oc.
__global__ void __launch_bounds__(256)
conv1x1_qk_k(const float* __restrict__ in, const float* __restrict__ w,
             const float* __restrict__ bias, __half* __restrict__ out, int sel)
{
    constexpr int SWP = 68;
    __shared__ __align__(16) float sX[16 * 128];
    __shared__ __align__(16) float sW[16 * SWP];

    const int i  = blockIdx.x;
    const int b  = blockIdx.z;
    const int apar = (i + sel) & 1;
    const int pxb = (threadIdx.x & 31) * 4;   // active-px base
    const int ocb = (threadIdx.x >> 5) * 8;

    ull acc[16];
#pragma unroll
    for (int t = 0; t < 16; t++) acc[t] = 0ULL;

    const float* inb = in + (size_t)b * 64 * HWC + (size_t)i * Ww;

    for (int cc = 0; cc < 64; cc += 16) {
        __syncthreads();
        // coalesced: float4 over 4 dense cols -> 2 active px each
        for (int t = threadIdx.x; t < 1024; t += 256) {
            int ci = t >> 6, g = t & 63;
            float4 v = *(const float4*)&inb[(size_t)(cc + ci) * HWC + 4 * g];
            sX[ci * 128 + 2 * g + 0] = apar ? v.y : v.x;
            sX[ci * 128 + 2 * g + 1] = apar ? v.w : v.z;
        }
        for (int t = threadIdx.x; t < 256; t += 256) {
            int oc = t >> 2, u = t & 3;
            float4 wv = *(const float4*)&w[(size_t)oc * 64 + cc + u * 4];
            sW[(u * 4 + 0) * SWP + oc] = wv.x;
            sW[(u * 4 + 1) * SWP + oc] = wv.y;
            sW[(u * 4 + 2) * SWP + oc] = wv.z;
            sW[(u * 4 + 3) * SWP + oc] = wv.w;
        }
        __syncthreads();
#pragma unroll
        for (int ci = 0; ci < 16; ci++) {
            float4 xv = *(const float4*)&sX[ci * 128 + pxb];
            ull xx[4];
            xx[0] = bcast2(xv.x); xx[1] = bcast2(xv.y);
            xx[2] = bcast2(xv.z); xx[3] = bcast2(xv.w);
#pragma unroll
            for (int o4 = 0; o4 < 2; o4++) {
                ulonglong2 wv = *(const ulonglong2*)&sW[ci * SWP + ocb + o4 * 4];
#pragma unroll
                for (int l = 0; l < 4; l++) {
                    fma2(acc[(o4 * 2 + 0) * 4 + l], wv.x, xx[l]);
                    fma2(acc[(o4 * 2 + 1) * 4 + l], wv.y, xx[l]);
                }
            }
        }
    }

    // epilogue: one 16B store (8 dense px) per oc-row per thread
    __half* ob = out + ((size_t)b * 64 + ocb) * HWC + (size_t)i * Ww + 2 * pxb;
#pragma unroll
    for (int op = 0; op < 4; op++) {
        float fl[4], fh[4];
#pragma unroll
        for (int l = 0; l < 4; l++) unpack2(fl[l], fh[l], acc[op * 4 + l]);
        const int o0 = 2 * op, o1 = 2 * op + 1;
        const float b0 = __ldg(&bias[ocb + o0]);
        const float b1 = __ldg(&bias[ocb + o1]);
        const __half hb0 = __float2half_rn(b0);
        const __half hb1 = __float2half_rn(b1);
        uint4 u0, u1;
        uint32_t* p0 = (uint32_t*)&u0;
        uint32_t* p1 = (uint32_t*)&u1;
#pragma unroll
        for (int l = 0; l < 4; l++) {
            __half hv0 = __float2half_rn(fl[l] + b0);
            __half hv1 = __float2half_rn(fh[l] + b1);
            __half2 w0 = apar ? __halves2half2(hb0, hv0) : __halves2half2(hv0, hb0);
            __half2 w1 = apar ? __halves2half2(hb1, hv1) : __halves2half2(hv1, hb1);
            p0[l] = *(uint32_t*)&w0;
            p1[l] = *(uint32_t*)&w1;
        }
        *(uint4*)&ob[(size_t)o0 * HWC] = u0;
        *(uint4*)&ob[(size_t)o1 * HWC] = u1;
    }
}

// ---------------- depthwise 3x3 + checkerboard squeeze (fp16 in, wide loads) ----------------
// block 128 thr = squeezed row; 4 output rows per block. grid (Hh/4, Bn*Cd).
__global__ void __launch_bounds__(128)
dw3x3_squeeze_k(const __half* __restrict__ in, const float* __restrict__ w,
                const float* __restrict__ bias, float* __restrict__ out, int type)
{
    __shared__ float sR[6][256];
    const int i0 = blockIdx.x * 4;
    const int bc = blockIdx.y;
    const int c  = bc & 63;
    const int jc = threadIdx.x;
    const __half* inp = in + (size_t)bc * HWC;

    // stage rows i0-1 .. i0+4 via uint4 (8 halfs = 16B per lane)
    for (int t = threadIdx.x; t < 192; t += 128) {
        int r = t >> 5, g = t & 31;
        int ii = i0 - 1 + r;
        float4 lo = make_float4(0.f, 0.f, 0.f, 0.f);
        float4 hi = make_float4(0.f, 0.f, 0.f, 0.f);
        if (ii >= 0 && ii < Hh) ld8h(&inp[ii * Ww + g * 8], lo, hi);
        *(float4*)&sR[r][g * 8]     = lo;
        *(float4*)&sR[r][g * 8 + 4] = hi;
    }
    __syncthreads();

    float wk[9];
#pragma unroll
    for (int k = 0; k < 9; k++) wk[k] = __ldg(&w[c * 9 + k]);
    const float bv = __ldg(&bias[c]);

#pragma unroll
    for (int ry = 0; ry < 4; ry++) {
        const int i   = i0 + ry;
        const int sel = type ? (i & 1) : (1 - (i & 1));
        const int jf  = 2 * jc + sel;
        float acc = bv;
#pragma unroll
        for (int r = 0; r < 3; r++) {
            const float* row = sR[ry + r];
#pragma unroll
            for (int dx = -1; dx <= 1; dx++) {
                int jj = jf + dx;
                if (jj >= 0 && jj < Ww)
                    acc += wk[r * 3 + dx + 1] * row[jj];
            }
        }
        out[(size_t)bc * Nh + i * Wh + jc] = acc;
    }
}

// ---------------- depthwise 3x3 + gelu (fp16 in/out, wide loads) ----------------
// block 256 thr = full row; 4 output rows per block. grid (Hh/4, Bn*256)
__global__ void __launch_bounds__(256)
dw3x3_gelu_k(const __half* __restrict__ in, const float* __restrict__ w,
             const float* __restrict__ bias, __half* __restrict__ out)
{
    __shared__ float sR[6][256];
    const int i0 = blockIdx.x * 4;
    const int bc = blockIdx.y;
    const int c  = bc & 255;
    const int j  = threadIdx.x;
    const __half* inp = in + (size_t)bc * HWC;

    for (int t = threadIdx.x; t < 192; t += 256) {
        int r = t >> 5, g = t & 31;
        int ii = i0 - 1 + r;
        float4 lo = make_float4(0.f, 0.f, 0.f, 0.f);
        float4 hi = make_float4(0.f, 0.f, 0.f, 0.f);
        if (ii >= 0 && ii < Hh) ld8h(&inp[ii * Ww + g * 8], lo, hi);
        *(float4*)&sR[r][g * 8]     = lo;
        *(float4*)&sR[r][g * 8 + 4] = hi;
    }
    __syncthreads();

    float wk[9];
#pragma unroll
    for (int k = 0; k < 9; k++) wk[k] = __ldg(&w[c * 9 + k]);
    const float bv = __ldg(&bias[c]);

#pragma unroll
    for (int ry = 0; ry < 4; ry++) {
        float acc = bv;
#pragma unroll
        for (int r = 0; r < 3; r++) {
            const float* row = sR[ry + r];
#pragma unroll
            for (int dx = -1; dx <= 1; dx++) {
                int jj = j + dx;
                if (jj >= 0 && jj < Ww)
                    acc += wk[r * 3 + dx + 1] * row[jj];
            }
        }
        // per-warp: 32 consecutive 2B halves = 64B, fully coalesced
        out[(size_t)bc * HWC + (i0 + ry) * Ww + j] = __float2half_rn(gelu_f(acc));
    }
}

// ---------------- k row stats: max and sum(exp(k-max)) per (b,c) row ----------------
__global__ void ksum_k(const float* __restrict__ ks)
{
    const size_t base = (size_t)blockIdx.x * Nh;
    __shared__ float red[256];
    float mx = -1e30f;
    for (int n = threadIdx.x; n < Nh; n += 256) mx = fmaxf(mx, ks[base + n]);
    red[threadIdx.x] = mx; __syncthreads();
    for (int s = 128; s > 0; s >>= 1) {
        if (threadIdx.x < s) red[threadIdx.x] = fmaxf(red[threadIdx.x], red[threadIdx.x + s]);
        __syncthreads();
    }
    mx = red[0]; __syncthreads();
    float sum = 0.f;
    for (int n = threadIdx.x; n < Nh; n += 256) sum += __expf(ks[base + n] - mx);
    red[threadIdx.x] = sum; __syncthreads();
    for (int s = 128; s > 0; s >>= 1) {
        if (threadIdx.x < s) red[threadIdx.x] += red[threadIdx.x + s];
        __syncthreads();
    }
    if (threadIdx.x == 0) { g_kmax[blockIdx.x] = mx; g_kz[blockIdx.x] = red[0]; }
}

// ---------------- ctx partials on exp(k-max): g_ctxp[bh][split][d*16+e] ----------------
__global__ void ctx_k(const float* __restrict__ ks, const float* __restrict__ vs)
{
    const int bh = blockIdx.x;
    const int b = bh >> 2, hd = bh & 3;
    const int d = threadIdx.x >> 4, e = threadIdx.x & 15;
    const float* kb = ks + ((size_t)b * Cd + hd * 16) * Nh;
    const float* vb = vs + ((size_t)b * Cd + hd * 16) * Nh;
    __shared__ __align__(16) float sk[16 * 260];
    __shared__ __align__(16) float sv[16 * 260];
    __shared__ float s_mx[16];
    if (threadIdx.x < 16)
        s_mx[threadIdx.x] = g_kmax[b * Cd + hd * 16 + threadIdx.x];
    float acc = 0.f;
    const int n00 = blockIdx.y * 4096;
    for (int n0 = n00; n0 < n00 + 4096; n0 += 256) {
        __syncthreads();
        for (int t = threadIdx.x; t < 4096; t += 256) {
            int dd = t >> 8, nn = t & 255;
            sk[dd * 260 + nn] = __expf(kb[(size_t)dd * Nh + n0 + nn] - s_mx[dd]);
            sv[dd * 260 + nn] = vb[(size_t)dd * Nh + n0 + nn];
        }
        __syncthreads();
#pragma unroll 4
        for (int nn = 0; nn < 256; nn++)
            acc += sk[d * 260 + nn] * sv[e * 260 + nn];
    }
    g_ctxp[((size_t)bh * 8 + blockIdx.y) * 256 + d * 16 + e] = acc;
}

// ---------------- att (SQUEEZED) with fused q-softmax + k normalization ----------------
__global__ void att_k(const float* __restrict__ qs, float* __restrict__ att_sq)
{
    const int bh = blockIdx.y;
    const int b = bh >> 2, hd = bh & 3;
    __shared__ float sc[256];
    {
        float s = 0.f;
#pragma unroll
        for (int sp = 0; sp < 8; sp++)
            s += g_ctxp[((size_t)bh * 8 + sp) * 256 + threadIdx.x];
        sc[threadIdx.x] = s / g_kz[b * Cd + hd * 16 + (threadIdx.x >> 4)];
    }
    __syncthreads();
    const int n = blockIdx.x * 256 + threadIdx.x;
    float qv[16];
    const float* qb = qs + ((size_t)b * Cd + hd * 16) * Nh + n;
    float mx = -1e30f;
#pragma unroll
    for (int d = 0; d < 16; d++) { qv[d] = qb[(size_t)d * Nh]; mx = fmaxf(mx, qv[d]); }
    float ssum = 0.f;
#pragma unroll
    for (int d = 0; d < 16; d++) { qv[d] = __expf(qv[d] - mx); ssum += qv[d]; }
    float inv = 1.0f / ssum;
#pragma unroll
    for (int d = 0; d < 16; d++) qv[d] *= inv;
    float* ab = att_sq + ((size_t)b * Cd + hd * 16) * Nh + n;
#pragma unroll
    for (int e = 0; e < 16; e++) {
        float s = 0.f;
#pragma unroll
        for (int d = 0; d < 16; d++) s += sc[d * 16 + e] * qv[d];
        ab[(size_t)e * Nh] = s;
    }
}

// ---------------- SPARSE 5x5 conv 64->128 on checkerboard input, fp32x2 ----------------
__global__ void __launch_bounds__(256)
conv5x5_sp_k(const float* __restrict__ in, const float* __restrict__ w,
             const float* __restrict__ bias, float* __restrict__ out)
{
    constexpr int CK = 4;
    __shared__ __align__(16) float sSq[CK * 240];
    __shared__ __align__(16) float sW[CK * 400];
    const int bz = blockIdx.z;
    const int b = bz >> 3, ocg = bz & 7;
    const int wid  = threadIdx.x >> 5;
    const int oq   = wid >> 1;
    const int qc   = wid & 1;
    const int lane = threadIdx.x & 31;
    const int py   = lane >> 1;
    const int m    = (lane & 1) * 4;
    const int x0 = blockIdx.x * 16, y0 = blockIdx.y * 16;
    const int p  = qc ^ (py & 1);

    ull acc[8];
    {
        float b0 = __ldg(&bias[ocg * 16 + oq * 4 + 0]);
        float b1 = __ldg(&bias[ocg * 16 + oq * 4 + 1]);
        float b2 = __ldg(&bias[ocg * 16 + oq * 4 + 2]);
        float b3 = __ldg(&bias[ocg * 16 + oq * 4 + 3]);
        ull p01 = pack2(b0, b1), p23 = pack2(b2, b3);
#pragma unroll
        for (int l = 0; l < 4; l++) { acc[l] = p01; acc[4 + l] = p23; }
    }

    const float* inb = in + (size_t)b * Cd * Nh;
    for (int cc = 0; cc < Cd; cc += CK) {
        __syncthreads();
#pragma unroll
        for (int c4 = 0; c4 < CK; c4++) {
            const int ci = cc + c4;
            for (int t = threadIdx.x; t < 200; t += 256) {
                int r = t / 10, s = t - r * 10;
                int ii = y0 - 2 + r;
                int jc = (x0 >> 1) - 1 + s;
                float v = 0.f;
                if (ii >= 0 && ii < Hh && jc >= 0 && jc < Wh)
                    v = inb[(size_t)ci * Nh + ii * Wh + jc];
                sSq[c4 * 240 + r * 12 + s] = v;
            }
            for (int t = threadIdx.x; t < 400; t += 256) {
                int ol = t & 15, k = t >> 4;
                sW[c4 * 400 + k * 16 + ol] = w[((size_t)(ocg * 16 + ol) * Cd + ci) * 25 + k];
            }
        }
        __syncthreads();
#pragma unroll
        for (int c4 = 0; c4 < CK; c4++) {
            const float* tile = &sSq[c4 * 240];
            const float* wt   = &sW[c4 * 400];
#pragma unroll
            for (int ky = 0; ky < 5; ky++) {
                const float* row = &tile[(py + ky) * 12 + m];
                if (((ky + qc) & 1) == 0) {
                    float4 a = *(const float4*)row;
                    ull xx[6];
                    xx[0] = bcast2(a.x); xx[1] = bcast2(a.y);
                    xx[2] = bcast2(a.z); xx[3] = bcast2(a.w);
                    xx[4] = bcast2(row[4]); xx[5] = bcast2(row[5]);
#pragma unroll
                    for (int kxh = 0; kxh < 3; kxh++) {
                        ulonglong2 wv = *(const ulonglong2*)&wt[(ky * 5 + 2 * kxh) * 16 + oq * 4];
#pragma unroll
                        for (int l = 0; l < 4; l++) {
                            fma2(acc[l],     wv.x, xx[l + kxh]);
                            fma2(acc[4 + l], wv.y, xx[l + kxh]);
                        }
                    }
                } else {
                    const float* rowp = row + p;
                    ull xx[5];
#pragma unroll
                    for (int j = 0; j < 5; j++) xx[j] = bcast2(rowp[j]);
#pragma unroll
                    for (int kxh = 0; kxh < 2; kxh++) {
                        ulonglong2 wv = *(const ulonglong2*)&wt[(ky * 5 + 2 * kxh + 1) * 16 + oq * 4];
#pragma unroll
                        for (int l = 0; l < 4; l++) {
                            fma2(acc[l],     wv.x, xx[l + kxh]);
                            fma2(acc[4 + l], wv.y, xx[l + kxh]);
                        }
                    }
                }
            }
        }
    }

    float* ob = out + ((size_t)b * 128 + ocg * 16 + oq * 4) * HWC
                    + (size_t)(y0 + py) * Ww + x0 + p + 2 * m;
#pragma unroll
    for (int l = 0; l < 4; l++) {
        float v0, v1, v2, v3;
        unpack2(v0, v1, acc[l]);
        unpack2(v2, v3, acc[4 + l]);
        ob[0 * (size_t)HWC + 2 * l] = v0;
        ob[1 * (size_t)HWC + 2 * l] = v1;
        ob[2 * (size_t)HWC + 2 * l] = v2;
        ob[3 * (size_t)HWC + 2 * l] = v3;
    }
}

// ---------------- driver ----------------
extern "C" void kernel_launch(void* const* d_in, const int* in_sizes, int n_in,
                              void* d_out, int out_size)
{
    const float* x1  = (const float*)d_in[0];
    const float* x2  = (const float*)d_in[1];
    const float* q1w = (const float*)d_in[2],  *q1b = (const float*)d_in[3];
    const float* q2w = (const float*)d_in[4],  *q2b = (const float*)d_in[5];
    const float* k1w = (const float*)d_in[6],  *k1b = (const float*)d_in[7];
    const float* k2w = (const float*)d_in[8],  *k2b = (const float*)d_in[9];
    const float* v1w = (const float*)d_in[10], *v1b = (const float*)d_in[11];
    const float* v2w = (const float*)d_in[12], *v2b = (const float*)d_in[13];
    const float* rw  = (const float*)d_in[14], *rb  = (const float*)d_in[15];
    const float* m1w = (const float*)d_in[16], *m1b = (const float*)d_in[17];
    const float* m2w = (const float*)d_in[18], *m2b = (const float*)d_in[19];
    const float* m3w = (const float*)d_in[20], *m3b = (const float*)d_in[21];
    float* out = (float*)d_out;

    __half *t, *m1, *m2;
    float *qs, *ks, *vs, *att, *attn;
    cudaGetSymbolAddress((void**)&t,    g_t);
    cudaGetSymbolAddress((void**)&qs,   g_qs);
    cudaGetSymbolAddress((void**)&ks,   g_ks);
    cudaGetSymbolAddress((void**)&vs,   g_vs);
    cudaGetSymbolAddress((void**)&att,  g_att);
    cudaGetSymbolAddress((void**)&attn, g_attn);
    cudaGetSymbolAddress((void**)&m1,   g_m1);
    cudaGetSymbolAddress((void**)&m2,   g_m2);

    // q/k: active-parity-only 1x1 conv (exact) -> depthwise 3x3 + squeeze
    conv1x1_qk_k<<<dim3(Hh, 1, Bn), 256>>>(x1, q1w, q1b, t, 0);               // keep (i+j) even
    dw3x3_squeeze_k<<<dim3(Hh / 4, Bn * Cd), 128>>>(t, q2w, q2b, qs, 1);      // nonanchor squeeze
    conv1x1_qk_k<<<dim3(Hh, 1, Bn), 256>>>(x1, k1w, k1b, t, 1);               // keep (i+j) odd
    dw3x3_squeeze_k<<<dim3(Hh / 4, Bn * Cd), 128>>>(t, k2w, k2b, ks, 0);      // anchor squeeze
    conv1x1_v2_k<float, __half, 64, 64, 64, 0>
        <<<dim3(HWC / 128, 1, Bn), 256>>>(x2, v1w, v1b, nullptr, t);          // v: no mask
    dw3x3_squeeze_k<<<dim3(Hh / 4, Bn * Cd), 128>>>(t, v2w, v2b, vs, 0);      // anchor squeeze

    // k-softmax fused: row stats, ctx on exp(k-max), att divides by Z
    ksum_k<<<Bn * Cd, 256>>>(ks);
    ctx_k<<<dim3(Bn * 4, 8), 256>>>(ks, vs);
    att_k<<<dim3(Nh / 256, Bn * 4), 256>>>(qs, att);

    // attention = sparse conv5x5(att)
    conv5x5_sp_k<<<dim3(Ww / 16, Hh / 16, Bn * 8), 256>>>(att, rw, rb, attn);

    // MLP (fp32 math, fp16 intermediates with 16B loads): m1 -> dw3x3 -> m3
    conv1x1_v2_k<float, __half, 128, 256, 128, 1>
        <<<dim3(HWC / 128, 2, Bn), 256>>>(attn, m1w, m1b, nullptr, m1);
    dw3x3_gelu_k<<<dim3(Hh / 4, Bn * 256), 256>>>(m1, m2w, m2b, m2);
    conv1x1_v2_k<__half, float, 256, 128, 128, 2>
        <<<dim3(HWC / 128, 1, Bn), 256>>>(m2, m3w, m3b, attn, out);
}